// round 11
// baseline (speedup 1.0000x reference)
#include <cuda_runtime.h>
#include <math.h>

#define VOCAB   32000
#define V4      8000                 // float4 per row
#define NROWS   4092                 // 4 * 1023
#define SEQ     1024
#define TPB     512
#define TAILQ   (V4 - 15 * TPB)      // 320 tail quads (= 10 full warps)
#define MAXCTA  256

__device__ double   g_part[MAXCTA];
__device__ unsigned g_cnt = 0;

// raw MUFU.LG2 (full-range log2 approx, single instruction)
__device__ __forceinline__ float lg2(float x) {
    float r; asm("lg2.approx.f32 %0, %1;" : "=f"(r) : "f"(x)); return r;
}

// scalar fast log (prologue only): degree-5, |abs err| <= 2e-4
__device__ __forceinline__ float lnfast(float x) {
    int i = __float_as_int(x);
    int k = (i - 0x3F2AAAAB) & 0xFF800000;
    float f = __int_as_float(i - k) - 1.0f;
    float P = 0.2f;
    P = fmaf(P, f, -0.25f);
    P = fmaf(P, f,  0.33333334f);
    P = fmaf(P, f, -0.5f);
    P = fmaf(P, f,  1.0f);
    return fmaf(f, P, (float)k * 8.2629582e-8f);
}

__device__ __forceinline__ float warp_sum(float v) {
    #pragma unroll
    for (int o = 16; o; o >>= 1) v += __shfl_xor_sync(0xFFFFFFFFu, v, o);
    return v;
}
__device__ __forceinline__ double warp_sum_d(double v) {
    #pragma unroll
    for (int o = 16; o; o >>= 1) v += __shfl_xor_sync(0xFFFFFFFFu, v, o);
    return v;
}

// one quad: 2-accumulator form
__device__ __forceinline__ void proc_quad(float4 v, float4 w, float& a0, float& a1) {
    a0 = fmaf(w.x, lg2(v.x), a0);
    a1 = fmaf(w.y, lg2(v.y), a1);
    a0 = fmaf(w.z, lg2(v.z), a0);
    a1 = fmaf(w.w, lg2(v.w), a1);
}

// row -> base quad pointer ( b*1024 + t = row + row/1023 )
__device__ __forceinline__ const float4* row_ptr(const float* p, int row) {
    int off = row + row / 1023;
    return reinterpret_cast<const float4*>(p + (size_t)off * VOCAB);
}

__global__ void __launch_bounds__(TPB, 1)
main_kernel(const float* __restrict__ p,
            const int*   __restrict__ dec,
            const float* __restrict__ th,
            float* __restrict__ out) {
    extern __shared__ float sth[];               // 32000 floats = 128 KB
    __shared__ float  redf[TPB / 32];
    __shared__ double redd[TPB / 32];
    __shared__ float  s_b[2];
    __shared__ int    s_last;

    const int tid = threadIdx.x;
    float4* sth4 = reinterpret_cast<float4*>(sth);
    const float4* th4 = reinterpret_cast<const float4*>(th);
    for (int i = tid; i < V4; i += TPB) sth4[i] = th4[i];
    __syncthreads();

    // ---- prologue: usum ----
    {
        float s = 0.f;
        for (int i = tid; i < VOCAB; i += TPB) s += sth[i];
        s = warp_sum(s);
        if ((tid & 31) == 0) redf[tid >> 5] = s;
        __syncthreads();
        if (tid == 0) {
            float t = 0.f;
            #pragma unroll
            for (int w = 0; w < TPB / 32; w++) t += redf[w];
            s_b[0] = t;
        }
        __syncthreads();
    }
    const float usum  = s_b[0];
    const float inv01 = 0.1f / usum;

    // ---- prologue: C1 = sum f(eps*u_v) ----
    {
        float c = 0.f;
        for (int i = tid; i < VOCAB; i += TPB) {
            float x = sth[i] * inv01;
            c += x * lnfast(x);
        }
        c = warp_sum(c);
        if ((tid & 31) == 0) redf[tid >> 5] = c;
        __syncthreads();
        if (tid == 0) {
            float t = 0.f;
            #pragma unroll
            for (int w = 0; w < TPB / 32; w++) t += redf[w];
            s_b[1] = t;
        }
        __syncthreads();
    }
    const float C1 = s_b[1];

    double accD = 0.0;

    // ---- label-dependent O(1)-per-row terms ----
    {
        for (int gid = blockIdx.x * TPB + tid; gid < NROWS; gid += gridDim.x * TPB) {
            const int b = gid / 1023;
            const int t = gid - b * 1023;
            const int l = __ldg(&dec[b * SEQ + t + 1]);
            if (l != 0) {
                float pl = __ldg(p + (size_t)(b * SEQ + t) * VOCAB + l);
                float x  = sth[l] * inv01;
                accD += (double)(C1
                                 - x * logf(x)
                                 + (x + 0.9f) * logf(x + 0.9f)
                                 - 0.9f * logf(pl));
            }
        }
    }

    // ---- bulk: rolling 4-quad-group pipeline (8 quads live max) ----
    const bool hasTail = (tid < TAILQ);          // 320 = 10 full warps
    float thrAcc = 0.f;

    int row = blockIdx.x;
    if (row < NROWS) {
        const float4* cp = row_ptr(p, row);
        // buffer A <- group 0
        float4 r0 = cp[tid           ];
        float4 r1 = cp[tid + 1 * TPB];
        float4 r2 = cp[tid + 2 * TPB];
        float4 r3 = cp[tid + 3 * TPB];

        while (true) {
            const int b   = row / 1023;
            const int lbl = __ldg(&dec[b * SEQ + (row - b * 1023) + 1]);

            const int  nrow  = row + gridDim.x;
            const bool valid = (nrow < NROWS);
            const float4* np = valid ? row_ptr(p, nrow) : cp;

            float a0 = 0.f, a1 = 0.f;

            // load G1 into B, process G0 (A)
            float4 s0 = cp[tid + 4 * TPB];
            float4 s1 = cp[tid + 5 * TPB];
            float4 s2 = cp[tid + 6 * TPB];
            float4 s3 = cp[tid + 7 * TPB];
            proc_quad(r0, sth4[tid          ], a0, a1);
            proc_quad(r1, sth4[tid + 1 * TPB], a0, a1);
            proc_quad(r2, sth4[tid + 2 * TPB], a0, a1);
            proc_quad(r3, sth4[tid + 3 * TPB], a0, a1);

            // load G2 into A, process G1 (B)
            r0 = cp[tid +  8 * TPB];
            r1 = cp[tid +  9 * TPB];
            r2 = cp[tid + 10 * TPB];
            r3 = cp[tid + 11 * TPB];
            proc_quad(s0, sth4[tid + 4 * TPB], a0, a1);
            proc_quad(s1, sth4[tid + 5 * TPB], a0, a1);
            proc_quad(s2, sth4[tid + 6 * TPB], a0, a1);
            proc_quad(s3, sth4[tid + 7 * TPB], a0, a1);

            // load G3 into B (quad 15 predicated), process G2 (A)
            s0 = cp[tid + 12 * TPB];
            s1 = cp[tid + 13 * TPB];
            s2 = cp[tid + 14 * TPB];
            if (hasTail) s3 = cp[tid + 15 * TPB];
            proc_quad(r0, sth4[tid +  8 * TPB], a0, a1);
            proc_quad(r1, sth4[tid +  9 * TPB], a0, a1);
            proc_quad(r2, sth4[tid + 10 * TPB], a0, a1);
            proc_quad(r3, sth4[tid + 11 * TPB], a0, a1);

            // load next row's G0 into A, process G3 (B)
            r0 = np[tid           ];
            r1 = np[tid + 1 * TPB];
            r2 = np[tid + 2 * TPB];
            r3 = np[tid + 3 * TPB];
            proc_quad(s0, sth4[tid + 12 * TPB], a0, a1);
            proc_quad(s1, sth4[tid + 13 * TPB], a0, a1);
            proc_quad(s2, sth4[tid + 14 * TPB], a0, a1);
            if (hasTail) proc_quad(s3, sth4[tid + 15 * TPB], a0, a1);

            if (lbl != 0) thrAcc += a0 + a1;

            if (!valid) break;
            row = nrow;
            cp  = np;
        }
    }

    // fold: accD += -eps/usum * ln2 * thrAcc
    accD += (double)thrAcc * (-0.1 * 0.6931471805599453 / (double)usum);

    // ---- per-CTA reduction ----
    accD = warp_sum_d(accD);
    if ((tid & 31) == 0) redd[tid >> 5] = accD;
    __syncthreads();
    if (tid == 0) {
        double t = 0.0;
        #pragma unroll
        for (int w = 0; w < TPB / 32; w++) t += redd[w];
        g_part[blockIdx.x] = t;
        __threadfence();
        unsigned old = atomicAdd(&g_cnt, 1u);
        s_last = (old == gridDim.x - 1) ? 1 : 0;
    }
    __syncthreads();

    // ---- last CTA finalizes ----
    if (s_last) {
        double v = (tid < (int)gridDim.x) ? g_part[tid] : 0.0;
        v = warp_sum_d(v);
        if ((tid & 31) == 0) redd[tid >> 5] = v;
        __syncthreads();
        if (tid == 0) {
            double t = 0.0;
            #pragma unroll
            for (int w = 0; w < TPB / 32; w++) t += redd[w];
            out[0] = (float)(t / (double)NROWS);
            g_cnt = 0;                 // reset for next graph replay
        }
    }
}

extern "C" void kernel_launch(void* const* d_in, const int* in_sizes, int n_in,
                              void* d_out, int out_size) {
    const int*   dec = nullptr;
    const float* p   = nullptr;
    const float* th  = nullptr;
    for (int i = 0; i < n_in; ++i) {
        if (in_sizes[i] == 4 * SEQ)    dec = (const int*)d_in[i];
        else if (in_sizes[i] == VOCAB) th  = (const float*)d_in[i];
        else                           p   = (const float*)d_in[i];
    }

    cudaFuncSetAttribute(main_kernel,
                         cudaFuncAttributeMaxDynamicSharedMemorySize,
                         VOCAB * (int)sizeof(float));

    int sms = 0;
    cudaDeviceGetAttribute(&sms, cudaDevAttrMultiProcessorCount, 0);
    if (sms <= 0) sms = 148;
    if (sms > MAXCTA) sms = MAXCTA;

    main_kernel<<<sms, TPB, VOCAB * sizeof(float)>>>(p, dec, th, (float*)d_out);
}